// round 14
// baseline (speedup 1.0000x reference)
#include <cuda_runtime.h>
#include <cuda_fp16.h>
#include <cstdint>

#define BN 128
#define HN 512
#define EN 256
#define VN 50000
#define SN 200
#define KT 1792     // 3H + E  (== GRU combined K)
#define GIN 1280    // 2H + E

// ---------------- device scratch (allocation-free rule: __device__ globals) ----
__device__ float g_u2p[32 * 1024];
__device__ float g_u2[1024];
__device__ float g_to[BN * KT];               // raw [ -- | context | emb_x ]
__device__ float g_gp[4][BN * 2048];          // GRU gate partials (K-split 4)
__device__ __align__(16) __half g_ah[BN * KT];    // to_out fp16 (logits A)
__device__ __align__(16) __half g_xh[BN * KT];    // GRU input X fp16

#define SWZ128(o) ((o) ^ (((o) >> 3) & 0x70))

__device__ __forceinline__ uint32_t smem_cast(const void* p) {
    return (uint32_t)__cvta_generic_to_shared(p);
}

#define CP_ASYNC16(s, g) asm volatile("cp.async.cg.shared.global [%0], [%1], 16;" :: "r"(s), "l"(g))
#define CP_COMMIT()      asm volatile("cp.async.commit_group;" ::: "memory")
#define CP_WAIT1()       asm volatile("cp.async.wait_group 1;" ::: "memory")
#define CP_WAIT0()       asm volatile("cp.async.wait_group 0;" ::: "memory")

// ---------------- kernel 0/1: u2 = attn_w[:, H:3H].T @ v -----------------------
__global__ void k_u2p(const float* __restrict__ aw, const float* __restrict__ v) {
    int g = blockIdx.x;
    for (int jj = 0; jj < 4; jj++) {
        int j = threadIdx.x + jj * 256;
        float acc = 0.f;
#pragma unroll
        for (int h = 0; h < 16; h++) {
            int hh = g * 16 + h;
            acc += v[hh] * aw[(size_t)hh * 1536 + 512 + j];
        }
        g_u2p[g * 1024 + j] = acc;
    }
}

__global__ void k_u2r() {
    int j = blockIdx.x * 256 + threadIdx.x;
    float s = 0.f;
#pragma unroll
    for (int g = 0; g < 32; g++) s += g_u2p[g * 1024 + j];
    g_u2[j] = s;
}

// ---------------- kernel 2: attention (512 thr) + GRU-input build --------------
#define ATTN_SMEM ((2 * 16 * 1024 + 1024) * 4)

__global__ __launch_bounds__(512) void k_attn(const float* __restrict__ enc,
                                              const int* __restrict__ x,
                                              const float* __restrict__ emb,
                                              const float* __restrict__ hid) {
    extern __shared__ float sm[];
    float* s_enc = sm;                    // [2][16*1024]
    float* s_u2 = sm + 2 * 16 * 1024;     // [1024]
    __shared__ float s_sc[16];
    int tid = threadIdx.x, wid = tid >> 5, lid = tid & 31;
    int b = blockIdx.x;
    const float* base = enc + (size_t)b * SN * 1024;

    for (int i = tid; i < 1024; i += 512) s_u2[i] = g_u2[i];

    {
        uint32_t sa = smem_cast(s_enc);
        for (int u = tid; u < 16 * 256; u += 512)
            CP_ASYNC16(sa + u * 16, (const char*)base + (size_t)u * 16);
        CP_COMMIT();
    }

    float m = -1e30f, sum = 0.f;
    float c0 = 0.f, c1 = 0.f;
    const int NT = 13;  // 12 x 16 + 8
    for (int t = 0; t < NT; t++) {
        int nr = (t == NT - 1) ? (SN - 16 * (NT - 1)) : 16;
        float* buf = s_enc + (t & 1) * 16 * 1024;
        if (t + 1 < NT) {
            int nr2 = (t + 1 == NT - 1) ? (SN - 16 * (NT - 1)) : 16;
            uint32_t sa = smem_cast(s_enc + ((t + 1) & 1) * 16 * 1024);
            const float* g = base + (size_t)(t + 1) * 16 * 1024;
            for (int u = tid; u < nr2 * 256; u += 512)
                CP_ASYNC16(sa + u * 16, (const char*)g + (size_t)u * 16);
            CP_COMMIT();
            CP_WAIT1();
        } else {
            CP_WAIT0();
        }
        __syncthreads();

        const float4* u24 = (const float4*)s_u2;
        if (wid < nr) {
            const float4* row = (const float4*)(buf + wid * 1024);
            float acc = 0.f;
#pragma unroll
            for (int q = lid; q < 256; q += 32) {
                float4 e = row[q], u = u24[q];
                acc += e.x * u.x + e.y * u.y + e.z * u.z + e.w * u.w;
            }
#pragma unroll
            for (int o = 16; o; o >>= 1) acc += __shfl_xor_sync(0xffffffffu, acc, o);
            if (lid == 0) s_sc[wid] = acc;
        }
        __syncthreads();

        float nm = m;
        for (int j = 0; j < nr; j++) nm = fmaxf(nm, s_sc[j]);
        float scl = expf(m - nm);
        c0 *= scl; c1 *= scl; sum *= scl;
        for (int j = 0; j < nr; j++) {
            float p = expf(s_sc[j] - nm);
            sum += p;
            const float* r = buf + j * 1024;
            c0 += p * r[tid];
            c1 += p * r[tid + 512];
        }
        m = nm;
        __syncthreads();
    }

    float inv = 1.0f / sum;
    c0 *= inv; c1 *= inv;

    g_to[b * KT + 512 + tid]  = c0;
    g_to[b * KT + 1024 + tid] = c1;

    int xb = b * KT;
    g_xh[xb + 256 + tid] = __float2half_rn(fmaxf(c0, 0.f));
    g_xh[xb + 768 + tid] = __float2half_rn(fmaxf(c1, 0.f));

    if (tid < 256) {
        float e = emb[(size_t)x[b] * EN + tid];
        g_to[b * KT + 1536 + tid] = e;
        g_xh[xb + tid] = __float2half_rn(fmaxf(e, 0.f));
    }
    float h0 = hid[b * HN + tid];
    g_xh[xb + 1280 + tid] = __float2half_rn(h0);
}

// ---------------- shared GEMM constants ----------------------------------------
#define ABYTES 16384
#define WROWF  68                      // 64 + 4 pad floats per row
#define NCHUNK 28

__device__ __forceinline__ void mma16816(float* c, const uint32_t* a, uint32_t b0, uint32_t b1) {
    asm volatile(
        "mma.sync.aligned.m16n8k16.row.col.f32.f16.f16.f32 "
        "{%0,%1,%2,%3}, {%4,%5,%6,%7}, {%8,%9}, {%0,%1,%2,%3};"
        : "+f"(c[0]), "+f"(c[1]), "+f"(c[2]), "+f"(c[3])
        : "r"(a[0]), "r"(a[1]), "r"(a[2]), "r"(a[3]), "r"(b0), "r"(b1));
}

// A staging (128 rows x 8 segs of 16B = 1024 slots), 256-thread version
__device__ __forceinline__ void stage_a256(int ch, uint32_t sbase, int tid, const char* ah) {
#pragma unroll
    for (int i = 0; i < 4; i++) {
        int q = tid + i * 256;
        int row = q >> 3, seg = q & 7;
        uint32_t sw = SWZ128((uint32_t)(row * 128 + seg * 16));
        CP_ASYNC16(sbase + sw, ah + (size_t)ch * 128 + (size_t)row * (KT * 2) + seg * 16);
    }
}

// ---------------- kernel 3: GRU gate GEMM, K-split 4-way (unchanged) -----------
#define GG_WBYTES (64 * WROWF * 4)
#define GG_SSTG   (ABYTES + GG_WBYTES)   // 33792
#define GG_SMEM   (2 * GG_SSTG)          // 67584

__global__ __launch_bounds__(256, 2) void k_ggemm(const float* __restrict__ wih,
                                                  const float* __restrict__ whh) {
    extern __shared__ char smem[];
    int tid = threadIdx.x, wid = tid >> 5, lid = tid & 31;
    int t = blockIdx.x >> 2;
    int ks = blockIdx.x & 3;
    int j0 = t * 64;
    int ch0 = (t >= 24) ? 20 : 0;
    int ch1 = (t >= 16 && t < 24) ? 20 : NCHUNK;
    int cl0 = max(ch0, ks * 7), cl1 = min(ch1, ks * 7 + 7);

    float* gp = g_gp[ks];

    if (cl0 >= cl1) {
        for (int i = tid; i < 128 * 64; i += 256) {
            int row = i >> 6, col = i & 63;
            gp[row * 2048 + j0 + col] = 0.f;
        }
        return;
    }

    int warpM = (wid & 1) * 64;
    int warpN = (wid >> 1) * 16;
    int lr = lid >> 2, lq = lid & 3;
    int lrow = lid & 15;
    int lcolh = (lid >> 4) * 16;

    uint32_t sb = smem_cast(smem);
    const char* ah = (const char*)g_xh;

    float c[4][2][4];
#pragma unroll
    for (int mt = 0; mt < 4; mt++)
#pragma unroll
        for (int nt = 0; nt < 2; nt++)
#pragma unroll
            for (int j = 0; j < 4; j++) c[mt][nt][j] = 0.f;

    auto stage_w = [&](int ch, uint32_t sbase) {
        uint32_t sa_w = sbase + ABYTES;
#pragma unroll
        for (int i = 0; i < 4; i++) {
            int u = tid + i * 256;
            int row = u >> 4, seg = u & 15;
            int j = j0 + row;
            const char* src;
            if (ch < 20) {
                src = (const char*)(wih + (size_t)j * GIN + ch * 64);
            } else {
                int wr = (j < 1024) ? j : j - 512;
                src = (const char*)(whh + (size_t)wr * HN + (ch - 20) * 64);
            }
            CP_ASYNC16(sa_w + row * (WROWF * 4) + seg * 16, src + seg * 16);
        }
    };

    stage_a256(cl0, sb, tid, ah);
    stage_w(cl0, sb);
    CP_COMMIT();
    if (cl0 + 1 < cl1) {
        stage_a256(cl0 + 1, sb + GG_SSTG, tid, ah);
        stage_w(cl0 + 1, sb + GG_SSTG);
        CP_COMMIT();
    }

    for (int ch = cl0; ch < cl1; ch++) {
        if (ch == cl1 - 1) { CP_WAIT0(); } else { CP_WAIT1(); }
        __syncthreads();

        int st = (ch - cl0) & 1;
        uint32_t sa_hi = sb + (uint32_t)st * GG_SSTG;
        const float* sW = (const float*)(smem + st * GG_SSTG + ABYTES);

#pragma unroll
        for (int s = 0; s < 4; s++) {
            uint32_t ahi[4][4];
#pragma unroll
            for (int mt = 0; mt < 4; mt++) {
                int row = warpM + mt * 16 + lrow;
                uint32_t off = SWZ128((uint32_t)(row * 128 + s * 32 + lcolh));
                asm volatile("ldmatrix.sync.aligned.m8n8.x4.shared.b16 {%0,%1,%2,%3}, [%4];"
                             : "=r"(ahi[mt][0]), "=r"(ahi[mt][1]), "=r"(ahi[mt][2]), "=r"(ahi[mt][3])
                             : "r"(sa_hi + off));
            }
#pragma unroll
            for (int nt = 0; nt < 2; nt++) {
                const float* wr = sW + (warpN + nt * 8 + lr) * WROWF + s * 16 + lq * 2;
                float2 w0 = *(const float2*)wr;
                float2 w1 = *(const float2*)(wr + 8);
                __half2 h0 = __floats2half2_rn(w0.x, w0.y);
                __half2 h1 = __floats2half2_rn(w1.x, w1.y);
                uint32_t bh0 = *(uint32_t*)&h0, bh1 = *(uint32_t*)&h1;
#pragma unroll
                for (int mt = 0; mt < 4; mt++) mma16816(c[mt][nt], ahi[mt], bh0, bh1);
            }
        }
        __syncthreads();
        if (ch + 2 < cl1) {
            uint32_t sbuf2 = sb + (uint32_t)((ch - cl0) & 1) * GG_SSTG;
            stage_a256(ch + 2, sbuf2, tid, ah);
            stage_w(ch + 2, sbuf2);
            CP_COMMIT();
        }
    }

#pragma unroll
    for (int nt = 0; nt < 2; nt++) {
        int col = j0 + warpN + nt * 8 + lq * 2;
#pragma unroll
        for (int mt = 0; mt < 4; mt++) {
            int row = warpM + mt * 16 + lr;
            gp[row * 2048 + col]           = c[mt][nt][0];
            gp[row * 2048 + col + 1]       = c[mt][nt][1];
            gp[(row + 8) * 2048 + col]     = c[mt][nt][2];
            gp[(row + 8) * 2048 + col + 1] = c[mt][nt][3];
        }
    }
}

// ---------------- kernel 4: GRU epilogue + fp16 conversion ---------------------
__global__ __launch_bounds__(256) void k_epiconv(const float* __restrict__ hid,
                                                 const float* __restrict__ bih,
                                                 const float* __restrict__ bhh,
                                                 float* __restrict__ outh) {
    __shared__ float s_h[HN];
    int tid = threadIdx.x;
    int b = blockIdx.x;
    int gb = b * 2048;

    for (int k = tid; k < HN; k += 256) {
        float gr = g_gp[0][gb + k] + g_gp[1][gb + k] + g_gp[2][gb + k] + g_gp[3][gb + k];
        float gz = g_gp[0][gb + 512 + k] + g_gp[1][gb + 512 + k] + g_gp[2][gb + 512 + k] + g_gp[3][gb + 512 + k];
        float gi = g_gp[0][gb + 1024 + k] + g_gp[1][gb + 1024 + k] + g_gp[2][gb + 1024 + k] + g_gp[3][gb + 1024 + k];
        float gh = g_gp[0][gb + 1536 + k] + g_gp[1][gb + 1536 + k] + g_gp[2][gb + 1536 + k] + g_gp[3][gb + 1536 + k];
        float h0 = hid[b * HN + k];
        float r = 1.f / (1.f + expf(-(gr + bih[k] + bhh[k])));
        float z = 1.f / (1.f + expf(-(gz + bih[512 + k] + bhh[512 + k])));
        float n = tanhf(gi + bih[1024 + k] + r * (gh + bhh[1024 + k]));
        float h = (1.f - z) * n + z * h0;
        s_h[k] = h;
        outh[b * HN + k] = h;
    }
    __syncthreads();

    for (int i = tid; i < KT; i += 256) {
        float v = (i < HN) ? s_h[i] : g_to[b * KT + i];
        g_ah[b * KT + i] = __float2half_rn(v);
    }
}

// ---------------- kernel 5: logits — persistent CTAs, continuous 3-stage pipe --
// grid = 304 (152 SMs x 2 CTAs). Each CTA walks tiles with stride 304 via a flat
// global-chunk loop; the staging cursor runs 2 chunks ahead and crosses tile
// boundaries, so the cp.async pipeline never drains between tiles. One
// __syncthreads per chunk (3-slot argument identical to the per-tile version).
#define LG_WBYTES (64 * WROWF * 4)       // 17408
#define LG_SSTG   (ABYTES + LG_WBYTES)   // 33792
#define LOG_SMEM  (3 * LG_SSTG)          // 101376
#define NTILES ((VN + 63) / 64)          // 782
#define LOG_GRID 304

__device__ __forceinline__ void stage_chunk_l(int ch, uint32_t sbase, int tid,
                                              const char* ah, const float* W, int v0) {
    stage_a256(ch, sbase, tid, ah);
    uint32_t sa_w = sbase + ABYTES;
#pragma unroll
    for (int i = 0; i < 4; i++) {
        int u = tid + i * 256;
        int row = u >> 4, seg = u & 15;
        int vr = v0 + row;
        if (vr >= VN) vr = VN - 1;
        CP_ASYNC16(sa_w + row * (WROWF * 4) + seg * 16,
                   (const char*)(W + (size_t)vr * KT + ch * 64) + seg * 16);
    }
    CP_COMMIT();
}

__global__ __launch_bounds__(256, 2) void k_logits(const float* __restrict__ W,
                                                   const float* __restrict__ bias,
                                                   float* __restrict__ out) {
    extern __shared__ char smem[];
    int tid = threadIdx.x, wid = tid >> 5, lid = tid & 31;
    int warpM = (wid & 1) * 64;
    int warpN = (wid >> 1) * 16;
    int lr = lid >> 2, lq = lid & 3;
    int lrow = lid & 15;
    int lcolh = (lid >> 4) * 16;

    uint32_t sb = smem_cast(smem);
    const char* ah = (const char*)g_ah;

    int n_tiles = (NTILES - blockIdx.x + LOG_GRID - 1) / LOG_GRID;
    int total = n_tiles * NCHUNK;

    float c[4][2][4];
#pragma unroll
    for (int mt = 0; mt < 4; mt++)
#pragma unroll
        for (int nt = 0; nt < 2; nt++)
#pragma unroll
            for (int j = 0; j < 4; j++) c[mt][nt][j] = 0.f;

    // staging cursor, runs 2 chunks ahead (crosses tile boundaries)
    int s_ch = 0, s_tile = blockIdx.x, s_v0 = blockIdx.x * 64;
#define ADV_S() do { if (++s_ch == NCHUNK) { s_ch = 0; s_tile += LOG_GRID; s_v0 = s_tile * 64; } } while (0)

    stage_chunk_l(s_ch, sb, tid, ah, W, s_v0);              ADV_S();
    stage_chunk_l(s_ch, sb + LG_SSTG, tid, ah, W, s_v0);    ADV_S();

    int st = 0;                 // compute slot = g % 3
    int ch = 0;                 // chunk within current tile
    int v0 = blockIdx.x * 64;   // current tile base
    int tile = blockIdx.x;

    for (int g = 0; g < total; g++) {
        if (g == total - 1) { CP_WAIT0(); } else { CP_WAIT1(); }
        __syncthreads();        // single barrier per chunk

        if (s_tile < NTILES) {
            int st2 = st + 2; if (st2 >= 3) st2 -= 3;
            stage_chunk_l(s_ch, sb + (uint32_t)st2 * LG_SSTG, tid, ah, W, s_v0);
            ADV_S();
        }

        uint32_t sa_hi = sb + (uint32_t)st * LG_SSTG;
        const float* sW = (const float*)(smem + st * LG_SSTG + ABYTES);

#pragma unroll
        for (int s = 0; s < 4; s++) {
            uint32_t ahi[4][4];
#pragma unroll
            for (int mt = 0; mt < 4; mt++) {
                int row = warpM + mt * 16 + lrow;
                uint32_t off = SWZ128((uint32_t)(row * 128 + s * 32 + lcolh));
                asm volatile("ldmatrix.sync.aligned.m8n8.x4.shared.b16 {%0,%1,%2,%3}, [%4];"
                             : "=r"(ahi[mt][0]), "=r"(ahi[mt][1]), "=r"(ahi[mt][2]), "=r"(ahi[mt][3])
                             : "r"(sa_hi + off));
            }
#pragma unroll
            for (int nt = 0; nt < 2; nt++) {
                const float* wr = sW + (warpN + nt * 8 + lr) * WROWF + s * 16 + lq * 2;
                float2 w0 = *(const float2*)wr;
                float2 w1 = *(const float2*)(wr + 8);
                __half2 h0 = __floats2half2_rn(w0.x, w0.y);
                __half2 h1 = __floats2half2_rn(w1.x, w1.y);
                uint32_t bh0 = *(uint32_t*)&h0, bh1 = *(uint32_t*)&h1;
#pragma unroll
                for (int mt = 0; mt < 4; mt++) mma16816(c[mt][nt], ahi[mt], bh0, bh1);
            }
        }
        if (++st == 3) st = 0;

        if (++ch == NCHUNK) {
            // tile epilogue: add bias, store, reset accumulators
#pragma unroll
            for (int nt = 0; nt < 2; nt++) {
                int col = v0 + warpN + nt * 8 + lq * 2;
                float b0 = 0.f, b1 = 0.f;
                if (col < VN) b0 = bias[col];
                if (col + 1 < VN) b1 = bias[col + 1];
#pragma unroll
                for (int mt = 0; mt < 4; mt++) {
                    int row = warpM + mt * 16 + lr;
                    if (col < VN) {
                        out[(size_t)row * VN + col]       = c[mt][nt][0] + b0;
                        out[(size_t)(row + 8) * VN + col] = c[mt][nt][2] + b0;
                    }
                    if (col + 1 < VN) {
                        out[(size_t)row * VN + col + 1]       = c[mt][nt][1] + b1;
                        out[(size_t)(row + 8) * VN + col + 1] = c[mt][nt][3] + b1;
                    }
                    c[mt][nt][0] = c[mt][nt][1] = c[mt][nt][2] = c[mt][nt][3] = 0.f;
                }
            }
            ch = 0;
            tile += LOG_GRID;
            v0 = tile * 64;
        }
    }
#undef ADV_S
}

// ---------------- launch --------------------------------------------------------
extern "C" void kernel_launch(void* const* d_in, const int* in_sizes, int n_in,
                              void* d_out, int out_size) {
    const int*   x      = (const int*)d_in[0];
    const float* hidden = (const float*)d_in[1];
    const float* enc    = (const float*)d_in[2];
    const float* emb    = (const float*)d_in[3];
    const float* attn_w = (const float*)d_in[4];
    // d_in[5] = attn_b (softmax-invariant, unused)
    const float* v      = (const float*)d_in[6];
    const float* w_ih   = (const float*)d_in[7];
    const float* w_hh   = (const float*)d_in[8];
    const float* b_ih   = (const float*)d_in[9];
    const float* b_hh   = (const float*)d_in[10];
    const float* out_w  = (const float*)d_in[11];
    const float* out_b  = (const float*)d_in[12];
    float* out = (float*)d_out;

    cudaFuncSetAttribute(k_attn, cudaFuncAttributeMaxDynamicSharedMemorySize, ATTN_SMEM);
    cudaFuncSetAttribute(k_ggemm, cudaFuncAttributeMaxDynamicSharedMemorySize, GG_SMEM);
    cudaFuncSetAttribute(k_logits, cudaFuncAttributeMaxDynamicSharedMemorySize, LOG_SMEM);

    k_u2p<<<32, 256>>>(attn_w, v);
    k_u2r<<<4, 256>>>();
    k_attn<<<BN, 512, ATTN_SMEM>>>(enc, x, emb, hidden);
    k_ggemm<<<128, 256, GG_SMEM>>>(w_ih, w_hh);
    k_epiconv<<<BN, 256>>>(hidden, b_ih, b_hh, out + (size_t)BN * VN);
    k_logits<<<LOG_GRID, 256, LOG_SMEM>>>(out_w, out_b, out);
}

// round 15
// speedup vs baseline: 1.0239x; 1.0239x over previous
#include <cuda_runtime.h>
#include <cuda_fp16.h>
#include <cstdint>

#define BN 128
#define HN 512
#define EN 256
#define VN 50000
#define SN 200
#define KT 1792     // 3H + E  (== GRU combined K)
#define GIN 1280    // 2H + E

// ---------------- device scratch (allocation-free rule: __device__ globals) ----
__device__ float g_u2p[32 * 1024];
__device__ float g_to[BN * KT];               // raw [ -- | context | emb_x ]
__device__ float g_gp[4][BN * 2048];          // GRU gate partials (K-split 4)
__device__ __align__(16) __half g_ah[BN * KT];    // to_out fp16 (logits A)
__device__ __align__(16) __half g_xh[BN * KT];    // GRU input X fp16

#define SWZ128(o) ((o) ^ (((o) >> 3) & 0x70))

__device__ __forceinline__ uint32_t smem_cast(const void* p) {
    return (uint32_t)__cvta_generic_to_shared(p);
}

#define CP_ASYNC16(s, g) asm volatile("cp.async.cg.shared.global [%0], [%1], 16;" :: "r"(s), "l"(g))
#define CP_COMMIT()      asm volatile("cp.async.commit_group;" ::: "memory")
#define CP_WAIT1()       asm volatile("cp.async.wait_group 1;" ::: "memory")
#define CP_WAIT0()       asm volatile("cp.async.wait_group 0;" ::: "memory")

// ---------------- kernel 0: u2 partials = attn_w[:, H:3H].T @ v ----------------
__global__ void k_u2p(const float* __restrict__ aw, const float* __restrict__ v) {
    int g = blockIdx.x;
    for (int jj = 0; jj < 4; jj++) {
        int j = threadIdx.x + jj * 256;
        float acc = 0.f;
#pragma unroll
        for (int h = 0; h < 16; h++) {
            int hh = g * 16 + h;
            acc += v[hh] * aw[(size_t)hh * 1536 + 512 + j];
        }
        g_u2p[g * 1024 + j] = acc;
    }
}

// ---------------- kernel 1: attention (512 thr) + GRU-input build --------------
// u2 reduction folded in: each CTA sums the 32 partials from L2 (cheap).
#define ATTN_SMEM ((2 * 16 * 1024 + 1024) * 4)

__global__ __launch_bounds__(512) void k_attn(const float* __restrict__ enc,
                                              const int* __restrict__ x,
                                              const float* __restrict__ emb,
                                              const float* __restrict__ hid) {
    extern __shared__ float sm[];
    float* s_enc = sm;                    // [2][16*1024]
    float* s_u2 = sm + 2 * 16 * 1024;     // [1024]
    __shared__ float s_sc[16];
    int tid = threadIdx.x, wid = tid >> 5, lid = tid & 31;
    int b = blockIdx.x;
    const float* base = enc + (size_t)b * SN * 1024;

    // prefetch tile 0 first so the u2 reduction overlaps the DRAM latency
    {
        uint32_t sa = smem_cast(s_enc);
        for (int u = tid; u < 16 * 256; u += 512)
            CP_ASYNC16(sa + u * 16, (const char*)base + (size_t)u * 16);
        CP_COMMIT();
    }

    // u2 reduction (32 partials, L2-resident)
    for (int i = tid; i < 1024; i += 512) {
        float s = 0.f;
#pragma unroll
        for (int g = 0; g < 32; g++) s += g_u2p[g * 1024 + i];
        s_u2[i] = s;
    }

    float m = -1e30f, sum = 0.f;
    float c0 = 0.f, c1 = 0.f;
    const int NT = 13;  // 12 x 16 + 8
    for (int t = 0; t < NT; t++) {
        int nr = (t == NT - 1) ? (SN - 16 * (NT - 1)) : 16;
        float* buf = s_enc + (t & 1) * 16 * 1024;
        if (t + 1 < NT) {
            int nr2 = (t + 1 == NT - 1) ? (SN - 16 * (NT - 1)) : 16;
            uint32_t sa = smem_cast(s_enc + ((t + 1) & 1) * 16 * 1024);
            const float* g = base + (size_t)(t + 1) * 16 * 1024;
            for (int u = tid; u < nr2 * 256; u += 512)
                CP_ASYNC16(sa + u * 16, (const char*)g + (size_t)u * 16);
            CP_COMMIT();
            CP_WAIT1();
        } else {
            CP_WAIT0();
        }
        __syncthreads();

        const float4* u24 = (const float4*)s_u2;
        if (wid < nr) {
            const float4* row = (const float4*)(buf + wid * 1024);
            float acc = 0.f;
#pragma unroll
            for (int q = lid; q < 256; q += 32) {
                float4 e = row[q], u = u24[q];
                acc += e.x * u.x + e.y * u.y + e.z * u.z + e.w * u.w;
            }
#pragma unroll
            for (int o = 16; o; o >>= 1) acc += __shfl_xor_sync(0xffffffffu, acc, o);
            if (lid == 0) s_sc[wid] = acc;
        }
        __syncthreads();

        float nm = m;
        for (int j = 0; j < nr; j++) nm = fmaxf(nm, s_sc[j]);
        float scl = expf(m - nm);
        c0 *= scl; c1 *= scl; sum *= scl;
        for (int j = 0; j < nr; j++) {
            float p = expf(s_sc[j] - nm);
            sum += p;
            const float* r = buf + j * 1024;
            c0 += p * r[tid];
            c1 += p * r[tid + 512];
        }
        m = nm;
        __syncthreads();
    }

    float inv = 1.0f / sum;
    c0 *= inv; c1 *= inv;

    g_to[b * KT + 512 + tid]  = c0;
    g_to[b * KT + 1024 + tid] = c1;

    int xb = b * KT;
    g_xh[xb + 256 + tid] = __float2half_rn(fmaxf(c0, 0.f));
    g_xh[xb + 768 + tid] = __float2half_rn(fmaxf(c1, 0.f));

    if (tid < 256) {
        float e = emb[(size_t)x[b] * EN + tid];
        g_to[b * KT + 1536 + tid] = e;
        g_xh[xb + tid] = __float2half_rn(fmaxf(e, 0.f));
    }
    float h0 = hid[b * HN + tid];
    g_xh[xb + 1280 + tid] = __float2half_rn(h0);
}

// ---------------- shared GEMM constants ----------------------------------------
#define ABYTES 16384
#define WROWF  68                      // 64 + 4 pad floats per row
#define NCHUNK 28

__device__ __forceinline__ void mma16816(float* c, const uint32_t* a, uint32_t b0, uint32_t b1) {
    asm volatile(
        "mma.sync.aligned.m16n8k16.row.col.f32.f16.f16.f32 "
        "{%0,%1,%2,%3}, {%4,%5,%6,%7}, {%8,%9}, {%0,%1,%2,%3};"
        : "+f"(c[0]), "+f"(c[1]), "+f"(c[2]), "+f"(c[3])
        : "r"(a[0]), "r"(a[1]), "r"(a[2]), "r"(a[3]), "r"(b0), "r"(b1));
}

// A staging (128 rows x 8 segs of 16B = 1024 slots), 256-thread version
__device__ __forceinline__ void stage_a256(int ch, uint32_t sbase, int tid, const char* ah) {
#pragma unroll
    for (int i = 0; i < 4; i++) {
        int q = tid + i * 256;
        int row = q >> 3, seg = q & 7;
        uint32_t sw = SWZ128((uint32_t)(row * 128 + seg * 16));
        CP_ASYNC16(sbase + sw, ah + (size_t)ch * 128 + (size_t)row * (KT * 2) + seg * 16);
    }
}

// ---------------- kernel 2: GRU gate GEMM, 32-col N-tiles, K-split 4 -----------
// G[128,2048] = X' @ Wc^T. cols 0:512 r, 512:1024 z, 1024:1536 i_n, 1536:2048 h_n.
// chunks 0..19 from w_ih; 20..27 from w_hh. grid = 64 n-tiles x 4 k-slices = 256.
#define GG_WBYTES (32 * WROWF * 4)       // 8704
#define GG_SSTG   (ABYTES + GG_WBYTES)   // 25088
#define GG_SMEM   (2 * GG_SSTG)          // 50176

__global__ __launch_bounds__(256, 2) void k_ggemm(const float* __restrict__ wih,
                                                  const float* __restrict__ whh) {
    extern __shared__ char smem[];
    int tid = threadIdx.x, wid = tid >> 5, lid = tid & 31;
    int t = blockIdx.x >> 2;            // n-tile 0..63 (32 cols each)
    int ks = blockIdx.x & 3;            // k-slice 0..3
    int j0 = t * 32;
    int ch0 = (t >= 48) ? 20 : 0;
    int ch1 = (t >= 32 && t < 48) ? 20 : NCHUNK;
    int cl0 = max(ch0, ks * 7), cl1 = min(ch1, ks * 7 + 7);

    float* gp = g_gp[ks];

    if (cl0 >= cl1) {                   // empty slice: zero the partial
        for (int i = tid; i < 128 * 32; i += 256) {
            int row = i >> 5, col = i & 31;
            gp[row * 2048 + j0 + col] = 0.f;
        }
        return;
    }

    int warpM = (wid & 3) * 32;         // 4 m-warps
    int warpN = (wid >> 2) * 16;        // 2 n-warps
    int lr = lid >> 2, lq = lid & 3;
    int lrow = lid & 15;
    int lcolh = (lid >> 4) * 16;

    uint32_t sb = smem_cast(smem);
    const char* ah = (const char*)g_xh;

    float c[2][2][4];
#pragma unroll
    for (int mt = 0; mt < 2; mt++)
#pragma unroll
        for (int nt = 0; nt < 2; nt++)
#pragma unroll
            for (int j = 0; j < 4; j++) c[mt][nt][j] = 0.f;

    auto stage_w = [&](int ch, uint32_t sbase) {
        uint32_t sa_w = sbase + ABYTES;
#pragma unroll
        for (int i = 0; i < 2; i++) {
            int u = tid + i * 256;
            int row = u >> 4, seg = u & 15;
            int j = j0 + row;
            const char* src;
            if (ch < 20) {
                src = (const char*)(wih + (size_t)j * GIN + ch * 64);
            } else {
                int wr = (j < 1024) ? j : j - 512;
                src = (const char*)(whh + (size_t)wr * HN + (ch - 20) * 64);
            }
            CP_ASYNC16(sa_w + row * (WROWF * 4) + seg * 16, src + seg * 16);
        }
    };

    stage_a256(cl0, sb, tid, ah);
    stage_w(cl0, sb);
    CP_COMMIT();
    if (cl0 + 1 < cl1) {
        stage_a256(cl0 + 1, sb + GG_SSTG, tid, ah);
        stage_w(cl0 + 1, sb + GG_SSTG);
        CP_COMMIT();
    }

    for (int ch = cl0; ch < cl1; ch++) {
        if (ch == cl1 - 1) { CP_WAIT0(); } else { CP_WAIT1(); }
        __syncthreads();

        int st = (ch - cl0) & 1;
        uint32_t sa_hi = sb + (uint32_t)st * GG_SSTG;
        const float* sW = (const float*)(smem + st * GG_SSTG + ABYTES);

#pragma unroll
        for (int s = 0; s < 4; s++) {
            uint32_t ahi[2][4];
#pragma unroll
            for (int mt = 0; mt < 2; mt++) {
                int row = warpM + mt * 16 + lrow;
                uint32_t off = SWZ128((uint32_t)(row * 128 + s * 32 + lcolh));
                asm volatile("ldmatrix.sync.aligned.m8n8.x4.shared.b16 {%0,%1,%2,%3}, [%4];"
                             : "=r"(ahi[mt][0]), "=r"(ahi[mt][1]), "=r"(ahi[mt][2]), "=r"(ahi[mt][3])
                             : "r"(sa_hi + off));
            }
#pragma unroll
            for (int nt = 0; nt < 2; nt++) {
                const float* wr = sW + (warpN + nt * 8 + lr) * WROWF + s * 16 + lq * 2;
                float2 w0 = *(const float2*)wr;
                float2 w1 = *(const float2*)(wr + 8);
                __half2 h0 = __floats2half2_rn(w0.x, w0.y);
                __half2 h1 = __floats2half2_rn(w1.x, w1.y);
                uint32_t bh0 = *(uint32_t*)&h0, bh1 = *(uint32_t*)&h1;
#pragma unroll
                for (int mt = 0; mt < 2; mt++) mma16816(c[mt][nt], ahi[mt], bh0, bh1);
            }
        }
        __syncthreads();
        if (ch + 2 < cl1) {
            uint32_t sbuf2 = sb + (uint32_t)((ch - cl0) & 1) * GG_SSTG;
            stage_a256(ch + 2, sbuf2, tid, ah);
            stage_w(ch + 2, sbuf2);
            CP_COMMIT();
        }
    }

#pragma unroll
    for (int nt = 0; nt < 2; nt++) {
        int col = j0 + warpN + nt * 8 + lq * 2;
#pragma unroll
        for (int mt = 0; mt < 2; mt++) {
            int row = warpM + mt * 16 + lr;
            gp[row * 2048 + col]           = c[mt][nt][0];
            gp[row * 2048 + col + 1]       = c[mt][nt][1];
            gp[(row + 8) * 2048 + col]     = c[mt][nt][2];
            gp[(row + 8) * 2048 + col + 1] = c[mt][nt][3];
        }
    }
}

// ---------------- kernel 3: GRU epilogue + fp16 conversion ---------------------
__global__ __launch_bounds__(256) void k_epiconv(const float* __restrict__ hid,
                                                 const float* __restrict__ bih,
                                                 const float* __restrict__ bhh,
                                                 float* __restrict__ outh) {
    __shared__ float s_h[HN];
    int tid = threadIdx.x;
    int b = blockIdx.x;
    int gb = b * 2048;

    for (int k = tid; k < HN; k += 256) {
        float gr = g_gp[0][gb + k] + g_gp[1][gb + k] + g_gp[2][gb + k] + g_gp[3][gb + k];
        float gz = g_gp[0][gb + 512 + k] + g_gp[1][gb + 512 + k] + g_gp[2][gb + 512 + k] + g_gp[3][gb + 512 + k];
        float gi = g_gp[0][gb + 1024 + k] + g_gp[1][gb + 1024 + k] + g_gp[2][gb + 1024 + k] + g_gp[3][gb + 1024 + k];
        float gh = g_gp[0][gb + 1536 + k] + g_gp[1][gb + 1536 + k] + g_gp[2][gb + 1536 + k] + g_gp[3][gb + 1536 + k];
        float h0 = hid[b * HN + k];
        float r = 1.f / (1.f + expf(-(gr + bih[k] + bhh[k])));
        float z = 1.f / (1.f + expf(-(gz + bih[512 + k] + bhh[512 + k])));
        float n = tanhf(gi + bih[1024 + k] + r * (gh + bhh[1024 + k]));
        float h = (1.f - z) * n + z * h0;
        s_h[k] = h;
        outh[b * HN + k] = h;
    }
    __syncthreads();

    for (int i = tid; i < KT; i += 256) {
        float v = (i < HN) ? s_h[i] : g_to[b * KT + i];
        g_ah[b * KT + i] = __float2half_rn(v);
    }
}

// ---------------- kernel 4: logits — R13 config (per-tile, 3-stage, 1 barrier) -
#define LG_WBYTES (64 * WROWF * 4)       // 17408
#define LG_SSTG   (ABYTES + LG_WBYTES)   // 33792
#define LOG_SMEM  (3 * LG_SSTG)          // 101376

__device__ __forceinline__ void stage_chunk_l(int ch, uint32_t sbase, int tid,
                                              const char* ah, const float* W, int v0) {
    stage_a256(ch, sbase, tid, ah);
    uint32_t sa_w = sbase + ABYTES;
#pragma unroll
    for (int i = 0; i < 4; i++) {
        int u = tid + i * 256;
        int row = u >> 4, seg = u & 15;
        int vr = v0 + row;
        if (vr >= VN) vr = VN - 1;
        CP_ASYNC16(sa_w + row * (WROWF * 4) + seg * 16,
                   (const char*)(W + (size_t)vr * KT + ch * 64) + seg * 16);
    }
    CP_COMMIT();
}

__global__ __launch_bounds__(256, 2) void k_logits(const float* __restrict__ W,
                                                   const float* __restrict__ bias,
                                                   float* __restrict__ out) {
    extern __shared__ char smem[];
    int tid = threadIdx.x, wid = tid >> 5, lid = tid & 31;
    int v0 = blockIdx.x * 64;
    int warpM = (wid & 1) * 64;
    int warpN = (wid >> 1) * 16;
    int lr = lid >> 2, lq = lid & 3;
    int lrow = lid & 15;
    int lcolh = (lid >> 4) * 16;

    uint32_t sb = smem_cast(smem);
    const char* ah = (const char*)g_ah;

    float c[4][2][4];
#pragma unroll
    for (int mt = 0; mt < 4; mt++)
#pragma unroll
        for (int nt = 0; nt < 2; nt++)
#pragma unroll
            for (int j = 0; j < 4; j++) c[mt][nt][j] = 0.f;

    stage_chunk_l(0, sb, tid, ah, W, v0);
    stage_chunk_l(1, sb + LG_SSTG, tid, ah, W, v0);

    int st = 0;                          // st = ch % 3
    for (int ch = 0; ch < NCHUNK; ch++) {
        if (ch == NCHUNK - 1) { CP_WAIT0(); } else { CP_WAIT1(); }
        __syncthreads();                 // single barrier per chunk

        if (ch + 2 < NCHUNK) {
            int st2 = st + 2; if (st2 >= 3) st2 -= 3;   // (ch+2) % 3
            stage_chunk_l(ch + 2, sb + (uint32_t)st2 * LG_SSTG, tid, ah, W, v0);
        }

        uint32_t sa_hi = sb + (uint32_t)st * LG_SSTG;
        const float* sW = (const float*)(smem + st * LG_SSTG + ABYTES);

#pragma unroll
        for (int s = 0; s < 4; s++) {
            uint32_t ahi[4][4];
#pragma unroll
            for (int mt = 0; mt < 4; mt++) {
                int row = warpM + mt * 16 + lrow;
                uint32_t off = SWZ128((uint32_t)(row * 128 + s * 32 + lcolh));
                asm volatile("ldmatrix.sync.aligned.m8n8.x4.shared.b16 {%0,%1,%2,%3}, [%4];"
                             : "=r"(ahi[mt][0]), "=r"(ahi[mt][1]), "=r"(ahi[mt][2]), "=r"(ahi[mt][3])
                             : "r"(sa_hi + off));
            }
#pragma unroll
            for (int nt = 0; nt < 2; nt++) {
                const float* wr = sW + (warpN + nt * 8 + lr) * WROWF + s * 16 + lq * 2;
                float2 w0 = *(const float2*)wr;
                float2 w1 = *(const float2*)(wr + 8);
                __half2 h0 = __floats2half2_rn(w0.x, w0.y);
                __half2 h1 = __floats2half2_rn(w1.x, w1.y);
                uint32_t bh0 = *(uint32_t*)&h0, bh1 = *(uint32_t*)&h1;
#pragma unroll
                for (int mt = 0; mt < 4; mt++) mma16816(c[mt][nt], ahi[mt], bh0, bh1);
            }
        }
        if (++st == 3) st = 0;
    }

    // epilogue: add bias, store
#pragma unroll
    for (int nt = 0; nt < 2; nt++) {
        int col = v0 + warpN + nt * 8 + lq * 2;
        float b0 = 0.f, b1 = 0.f;
        if (col < VN) b0 = bias[col];
        if (col + 1 < VN) b1 = bias[col + 1];
#pragma unroll
        for (int mt = 0; mt < 4; mt++) {
            int row = warpM + mt * 16 + lr;
            if (col < VN) {
                out[(size_t)row * VN + col]       = c[mt][nt][0] + b0;
                out[(size_t)(row + 8) * VN + col] = c[mt][nt][2] + b0;
            }
            if (col + 1 < VN) {
                out[(size_t)row * VN + col + 1]       = c[mt][nt][1] + b1;
                out[(size_t)(row + 8) * VN + col + 1] = c[mt][nt][3] + b1;
            }
        }
    }
}

// ---------------- launch --------------------------------------------------------
extern "C" void kernel_launch(void* const* d_in, const int* in_sizes, int n_in,
                              void* d_out, int out_size) {
    const int*   x      = (const int*)d_in[0];
    const float* hidden = (const float*)d_in[1];
    const float* enc    = (const float*)d_in[2];
    const float* emb    = (const float*)d_in[3];
    const float* attn_w = (const float*)d_in[4];
    // d_in[5] = attn_b (softmax-invariant, unused)
    const float* v      = (const float*)d_in[6];
    const float* w_ih   = (const float*)d_in[7];
    const float* w_hh   = (const float*)d_in[8];
    const float* b_ih   = (const float*)d_in[9];
    const float* b_hh   = (const float*)d_in[10];
    const float* out_w  = (const float*)d_in[11];
    const float* out_b  = (const float*)d_in[12];
    float* out = (float*)d_out;

    cudaFuncSetAttribute(k_attn, cudaFuncAttributeMaxDynamicSharedMemorySize, ATTN_SMEM);
    cudaFuncSetAttribute(k_ggemm, cudaFuncAttributeMaxDynamicSharedMemorySize, GG_SMEM);
    cudaFuncSetAttribute(k_logits, cudaFuncAttributeMaxDynamicSharedMemorySize, LOG_SMEM);

    k_u2p<<<32, 256>>>(attn_w, v);
    k_attn<<<BN, 512, ATTN_SMEM>>>(enc, x, emb, hidden);
    k_ggemm<<<256, 256, GG_SMEM>>>(w_ih, w_hh);
    k_epiconv<<<BN, 256>>>(hidden, b_ih, b_hh, out + (size_t)BN * VN);
    k_logits<<<(VN + 63) / 64, 256, LOG_SMEM>>>(out_w, out_b, out);
}

// round 16
// speedup vs baseline: 1.0380x; 1.0137x over previous
#include <cuda_runtime.h>
#include <cuda_fp16.h>
#include <cstdint>

#define BN 128
#define HN 512
#define EN 256
#define VN 50000
#define SN 200
#define KT 1792     // 3H + E  (== GRU combined K)
#define GIN 1280    // 2H + E

// ---------------- device scratch (allocation-free rule: __device__ globals) ----
__device__ float g_u2p[32 * 1024];
__device__ float g_gp[4][BN * 2048];          // GRU gate partials (K-split 4)
__device__ __align__(16) __half g_ah[BN * KT];    // to_out fp16 (logits A)
__device__ __align__(16) __half g_xh[BN * KT];    // GRU input X fp16

#define SWZ128(o) ((o) ^ (((o) >> 3) & 0x70))

__device__ __forceinline__ uint32_t smem_cast(const void* p) {
    return (uint32_t)__cvta_generic_to_shared(p);
}

#define CP_ASYNC16(s, g) asm volatile("cp.async.cg.shared.global [%0], [%1], 16;" :: "r"(s), "l"(g))
#define CP_COMMIT()      asm volatile("cp.async.commit_group;" ::: "memory")
#define CP_WAIT2()       asm volatile("cp.async.wait_group 2;" ::: "memory")
#define CP_WAIT1()       asm volatile("cp.async.wait_group 1;" ::: "memory")
#define CP_WAIT0()       asm volatile("cp.async.wait_group 0;" ::: "memory")

// ---------------- kernel 0: u2 partials = attn_w[:, H:3H].T @ v ----------------
__global__ void k_u2p(const float* __restrict__ aw, const float* __restrict__ v) {
    int g = blockIdx.x;
    for (int jj = 0; jj < 4; jj++) {
        int j = threadIdx.x + jj * 256;
        float acc = 0.f;
#pragma unroll
        for (int h = 0; h < 16; h++) {
            int hh = g * 16 + h;
            acc += v[hh] * aw[(size_t)hh * 1536 + 512 + j];
        }
        g_u2p[g * 1024 + j] = acc;
    }
}

// ---------------- kernel 1: attention (512 thr, 3-deep pipe) + A/X build -------
// u2 reduction folded in. Writes fp16 context/emb directly into g_ah (logits A
// cols 512:1792) and g_xh; GRU epilogue later fills g_ah cols 0:512.
#define ATTN_SMEM ((3 * 16 * 1024 + 1024) * 4)

__global__ __launch_bounds__(512) void k_attn(const float* __restrict__ enc,
                                              const int* __restrict__ x,
                                              const float* __restrict__ emb,
                                              const float* __restrict__ hid) {
    extern __shared__ float sm[];
    float* s_enc = sm;                    // [3][16*1024]
    float* s_u2 = sm + 3 * 16 * 1024;     // [1024]
    __shared__ float s_sc[16];
    int tid = threadIdx.x, wid = tid >> 5, lid = tid & 31;
    int b = blockIdx.x;
    const float* base = enc + (size_t)b * SN * 1024;
    const int NT = 13;  // 12 x 16 + 8

    // prefetch tiles 0,1 (overlaps the u2 reduction below)
#pragma unroll
    for (int t0 = 0; t0 < 2; t0++) {
        uint32_t sa = smem_cast(s_enc + t0 * 16 * 1024);
        const char* g = (const char*)(base + (size_t)t0 * 16 * 1024);
        for (int u = tid; u < 16 * 256; u += 512)
            CP_ASYNC16(sa + u * 16, g + (size_t)u * 16);
        CP_COMMIT();
    }

    // u2 reduction (32 partials, L2-resident)
    for (int i = tid; i < 1024; i += 512) {
        float s = 0.f;
#pragma unroll
        for (int g = 0; g < 32; g++) s += g_u2p[g * 1024 + i];
        s_u2[i] = s;
    }

    float m = -1e30f, sum = 0.f;
    float c0 = 0.f, c1 = 0.f;
    int slot = 0;   // t % 3
    for (int t = 0; t < NT; t++) {
        float* buf = s_enc + slot * 16 * 1024;
        if (t + 2 < NT) {
            int nr2 = (t + 2 == NT - 1) ? (SN - 16 * (NT - 1)) : 16;
            int s2 = slot + 2; if (s2 >= 3) s2 -= 3;   // (t+2) % 3
            uint32_t sa = smem_cast(s_enc + s2 * 16 * 1024);
            const char* g = (const char*)(base + (size_t)(t + 2) * 16 * 1024);
            for (int u = tid; u < nr2 * 256; u += 512)
                CP_ASYNC16(sa + u * 16, g + (size_t)u * 16);
            CP_COMMIT();
            CP_WAIT2();
        } else if (t + 1 < NT) {
            CP_WAIT1();
        } else {
            CP_WAIT0();
        }
        __syncthreads();

        int nr = (t == NT - 1) ? (SN - 16 * (NT - 1)) : 16;
        const float4* u24 = (const float4*)s_u2;
        if (wid < nr) {
            const float4* row = (const float4*)(buf + wid * 1024);
            float acc = 0.f;
#pragma unroll
            for (int q = lid; q < 256; q += 32) {
                float4 e = row[q], u = u24[q];
                acc += e.x * u.x + e.y * u.y + e.z * u.z + e.w * u.w;
            }
#pragma unroll
            for (int o = 16; o; o >>= 1) acc += __shfl_xor_sync(0xffffffffu, acc, o);
            if (lid == 0) s_sc[wid] = acc;
        }
        __syncthreads();

        float nm = m;
        for (int j = 0; j < nr; j++) nm = fmaxf(nm, s_sc[j]);
        float scl = expf(m - nm);
        c0 *= scl; c1 *= scl; sum *= scl;
        for (int j = 0; j < nr; j++) {
            float p = expf(s_sc[j] - nm);
            sum += p;
            const float* r = buf + j * 1024;
            c0 += p * r[tid];
            c1 += p * r[tid + 512];
        }
        m = nm;
        __syncthreads();
        if (++slot == 3) slot = 0;
    }

    float inv = 1.0f / sum;
    c0 *= inv; c1 *= inv;

    int xb = b * KT;
    // logits A: context cols 512:1536
    g_ah[xb + 512 + tid]  = __float2half_rn(c0);
    g_ah[xb + 1024 + tid] = __float2half_rn(c1);
    // GRU X: relu(ctx) cols 256:1280
    g_xh[xb + 256 + tid] = __float2half_rn(fmaxf(c0, 0.f));
    g_xh[xb + 768 + tid] = __float2half_rn(fmaxf(c1, 0.f));

    if (tid < 256) {
        float e = emb[(size_t)x[b] * EN + tid];
        g_ah[xb + 1536 + tid] = __float2half_rn(e);            // logits A: emb
        g_xh[xb + tid] = __float2half_rn(fmaxf(e, 0.f));       // GRU X: relu(emb)
    }
    float h0 = hid[b * HN + tid];
    g_xh[xb + 1280 + tid] = __float2half_rn(h0);               // GRU X: h0
}

// ---------------- shared GEMM constants ----------------------------------------
#define ABYTES 16384
#define WROWF  68                      // 64 + 4 pad floats per row
#define NCHUNK 28

__device__ __forceinline__ void mma16816(float* c, const uint32_t* a, uint32_t b0, uint32_t b1) {
    asm volatile(
        "mma.sync.aligned.m16n8k16.row.col.f32.f16.f16.f32 "
        "{%0,%1,%2,%3}, {%4,%5,%6,%7}, {%8,%9}, {%0,%1,%2,%3};"
        : "+f"(c[0]), "+f"(c[1]), "+f"(c[2]), "+f"(c[3])
        : "r"(a[0]), "r"(a[1]), "r"(a[2]), "r"(a[3]), "r"(b0), "r"(b1));
}

// A staging (128 rows x 8 segs of 16B = 1024 slots), 256-thread version
__device__ __forceinline__ void stage_a256(int ch, uint32_t sbase, int tid, const char* ah) {
#pragma unroll
    for (int i = 0; i < 4; i++) {
        int q = tid + i * 256;
        int row = q >> 3, seg = q & 7;
        uint32_t sw = SWZ128((uint32_t)(row * 128 + seg * 16));
        CP_ASYNC16(sbase + sw, ah + (size_t)ch * 128 + (size_t)row * (KT * 2) + seg * 16);
    }
}

// ---------------- kernel 2: GRU gate GEMM, 32-col N-tiles, K-split 4 -----------
#define GG_WBYTES (32 * WROWF * 4)       // 8704
#define GG_SSTG   (ABYTES + GG_WBYTES)   // 25088
#define GG_SMEM   (2 * GG_SSTG)          // 50176

__global__ __launch_bounds__(256, 2) void k_ggemm(const float* __restrict__ wih,
                                                  const float* __restrict__ whh) {
    extern __shared__ char smem[];
    int tid = threadIdx.x, wid = tid >> 5, lid = tid & 31;
    int t = blockIdx.x >> 2;            // n-tile 0..63 (32 cols each)
    int ks = blockIdx.x & 3;            // k-slice 0..3
    int j0 = t * 32;
    int ch0 = (t >= 48) ? 20 : 0;
    int ch1 = (t >= 32 && t < 48) ? 20 : NCHUNK;
    int cl0 = max(ch0, ks * 7), cl1 = min(ch1, ks * 7 + 7);

    float* gp = g_gp[ks];

    if (cl0 >= cl1) {                   // empty slice: zero the partial
        for (int i = tid; i < 128 * 32; i += 256) {
            int row = i >> 5, col = i & 31;
            gp[row * 2048 + j0 + col] = 0.f;
        }
        return;
    }

    int warpM = (wid & 3) * 32;         // 4 m-warps
    int warpN = (wid >> 2) * 16;        // 2 n-warps
    int lr = lid >> 2, lq = lid & 3;
    int lrow = lid & 15;
    int lcolh = (lid >> 4) * 16;

    uint32_t sb = smem_cast(smem);
    const char* ah = (const char*)g_xh;

    float c[2][2][4];
#pragma unroll
    for (int mt = 0; mt < 2; mt++)
#pragma unroll
        for (int nt = 0; nt < 2; nt++)
#pragma unroll
            for (int j = 0; j < 4; j++) c[mt][nt][j] = 0.f;

    auto stage_w = [&](int ch, uint32_t sbase) {
        uint32_t sa_w = sbase + ABYTES;
#pragma unroll
        for (int i = 0; i < 2; i++) {
            int u = tid + i * 256;
            int row = u >> 4, seg = u & 15;
            int j = j0 + row;
            const char* src;
            if (ch < 20) {
                src = (const char*)(wih + (size_t)j * GIN + ch * 64);
            } else {
                int wr = (j < 1024) ? j : j - 512;
                src = (const char*)(whh + (size_t)wr * HN + (ch - 20) * 64);
            }
            CP_ASYNC16(sa_w + row * (WROWF * 4) + seg * 16, src + seg * 16);
        }
    };

    stage_a256(cl0, sb, tid, ah);
    stage_w(cl0, sb);
    CP_COMMIT();
    if (cl0 + 1 < cl1) {
        stage_a256(cl0 + 1, sb + GG_SSTG, tid, ah);
        stage_w(cl0 + 1, sb + GG_SSTG);
        CP_COMMIT();
    }

    for (int ch = cl0; ch < cl1; ch++) {
        if (ch == cl1 - 1) { CP_WAIT0(); } else { CP_WAIT1(); }
        __syncthreads();

        int st = (ch - cl0) & 1;
        uint32_t sa_hi = sb + (uint32_t)st * GG_SSTG;
        const float* sW = (const float*)(smem + st * GG_SSTG + ABYTES);

#pragma unroll
        for (int s = 0; s < 4; s++) {
            uint32_t ahi[2][4];
#pragma unroll
            for (int mt = 0; mt < 2; mt++) {
                int row = warpM + mt * 16 + lrow;
                uint32_t off = SWZ128((uint32_t)(row * 128 + s * 32 + lcolh));
                asm volatile("ldmatrix.sync.aligned.m8n8.x4.shared.b16 {%0,%1,%2,%3}, [%4];"
                             : "=r"(ahi[mt][0]), "=r"(ahi[mt][1]), "=r"(ahi[mt][2]), "=r"(ahi[mt][3])
                             : "r"(sa_hi + off));
            }
#pragma unroll
            for (int nt = 0; nt < 2; nt++) {
                const float* wr = sW + (warpN + nt * 8 + lr) * WROWF + s * 16 + lq * 2;
                float2 w0 = *(const float2*)wr;
                float2 w1 = *(const float2*)(wr + 8);
                __half2 h0 = __floats2half2_rn(w0.x, w0.y);
                __half2 h1 = __floats2half2_rn(w1.x, w1.y);
                uint32_t bh0 = *(uint32_t*)&h0, bh1 = *(uint32_t*)&h1;
#pragma unroll
                for (int mt = 0; mt < 2; mt++) mma16816(c[mt][nt], ahi[mt], bh0, bh1);
            }
        }
        __syncthreads();
        if (ch + 2 < cl1) {
            uint32_t sbuf2 = sb + (uint32_t)((ch - cl0) & 1) * GG_SSTG;
            stage_a256(ch + 2, sbuf2, tid, ah);
            stage_w(ch + 2, sbuf2);
            CP_COMMIT();
        }
    }

#pragma unroll
    for (int nt = 0; nt < 2; nt++) {
        int col = j0 + warpN + nt * 8 + lq * 2;
#pragma unroll
        for (int mt = 0; mt < 2; mt++) {
            int row = warpM + mt * 16 + lr;
            gp[row * 2048 + col]           = c[mt][nt][0];
            gp[row * 2048 + col + 1]       = c[mt][nt][1];
            gp[(row + 8) * 2048 + col]     = c[mt][nt][2];
            gp[(row + 8) * 2048 + col + 1] = c[mt][nt][3];
        }
    }
}

// ---------------- kernel 3: GRU epilogue (gates + h only, 512 thr) -------------
__global__ __launch_bounds__(512) void k_epiconv(const float* __restrict__ hid,
                                                 const float* __restrict__ bih,
                                                 const float* __restrict__ bhh,
                                                 float* __restrict__ outh) {
    int k = threadIdx.x;        // one k per thread (HN == 512)
    int b = blockIdx.x;
    int gb = b * 2048;

    float gr = g_gp[0][gb + k] + g_gp[1][gb + k] + g_gp[2][gb + k] + g_gp[3][gb + k];
    float gz = g_gp[0][gb + 512 + k] + g_gp[1][gb + 512 + k] + g_gp[2][gb + 512 + k] + g_gp[3][gb + 512 + k];
    float gi = g_gp[0][gb + 1024 + k] + g_gp[1][gb + 1024 + k] + g_gp[2][gb + 1024 + k] + g_gp[3][gb + 1024 + k];
    float gh = g_gp[0][gb + 1536 + k] + g_gp[1][gb + 1536 + k] + g_gp[2][gb + 1536 + k] + g_gp[3][gb + 1536 + k];
    float h0 = hid[b * HN + k];
    float r = 1.f / (1.f + expf(-(gr + bih[k] + bhh[k])));
    float z = 1.f / (1.f + expf(-(gz + bih[512 + k] + bhh[512 + k])));
    float n = tanhf(gi + bih[1024 + k] + r * (gh + bhh[1024 + k]));
    float h = (1.f - z) * n + z * h0;
    outh[b * HN + k] = h;
    g_ah[b * KT + k] = __float2half_rn(h);     // logits A cols 0:512
}

// ---------------- kernel 4: logits — R13 config (per-tile, 3-stage, 1 barrier) -
#define LG_WBYTES (64 * WROWF * 4)       // 17408
#define LG_SSTG   (ABYTES + LG_WBYTES)   // 33792
#define LOG_SMEM  (3 * LG_SSTG)          // 101376

__device__ __forceinline__ void stage_chunk_l(int ch, uint32_t sbase, int tid,
                                              const char* ah, const float* W, int v0) {
    stage_a256(ch, sbase, tid, ah);
    uint32_t sa_w = sbase + ABYTES;
#pragma unroll
    for (int i = 0; i < 4; i++) {
        int u = tid + i * 256;
        int row = u >> 4, seg = u & 15;
        int vr = v0 + row;
        if (vr >= VN) vr = VN - 1;
        CP_ASYNC16(sa_w + row * (WROWF * 4) + seg * 16,
                   (const char*)(W + (size_t)vr * KT + ch * 64) + seg * 16);
    }
    CP_COMMIT();
}

__global__ __launch_bounds__(256, 2) void k_logits(const float* __restrict__ W,
                                                   const float* __restrict__ bias,
                                                   float* __restrict__ out) {
    extern __shared__ char smem[];
    int tid = threadIdx.x, wid = tid >> 5, lid = tid & 31;
    int v0 = blockIdx.x * 64;
    int warpM = (wid & 1) * 64;
    int warpN = (wid >> 1) * 16;
    int lr = lid >> 2, lq = lid & 3;
    int lrow = lid & 15;
    int lcolh = (lid >> 4) * 16;

    uint32_t sb = smem_cast(smem);
    const char* ah = (const char*)g_ah;

    float c[4][2][4];
#pragma unroll
    for (int mt = 0; mt < 4; mt++)
#pragma unroll
        for (int nt = 0; nt < 2; nt++)
#pragma unroll
            for (int j = 0; j < 4; j++) c[mt][nt][j] = 0.f;

    stage_chunk_l(0, sb, tid, ah, W, v0);
    stage_chunk_l(1, sb + LG_SSTG, tid, ah, W, v0);

    int st = 0;                          // st = ch % 3
    for (int ch = 0; ch < NCHUNK; ch++) {
        if (ch == NCHUNK - 1) { CP_WAIT0(); } else { CP_WAIT1(); }
        __syncthreads();                 // single barrier per chunk

        if (ch + 2 < NCHUNK) {
            int st2 = st + 2; if (st2 >= 3) st2 -= 3;   // (ch+2) % 3
            stage_chunk_l(ch + 2, sb + (uint32_t)st2 * LG_SSTG, tid, ah, W, v0);
        }

        uint32_t sa_hi = sb + (uint32_t)st * LG_SSTG;
        const float* sW = (const float*)(smem + st * LG_SSTG + ABYTES);

#pragma unroll
        for (int s = 0; s < 4; s++) {
            uint32_t ahi[4][4];
#pragma unroll
            for (int mt = 0; mt < 4; mt++) {
                int row = warpM + mt * 16 + lrow;
                uint32_t off = SWZ128((uint32_t)(row * 128 + s * 32 + lcolh));
                asm volatile("ldmatrix.sync.aligned.m8n8.x4.shared.b16 {%0,%1,%2,%3}, [%4];"
                             : "=r"(ahi[mt][0]), "=r"(ahi[mt][1]), "=r"(ahi[mt][2]), "=r"(ahi[mt][3])
                             : "r"(sa_hi + off));
            }
#pragma unroll
            for (int nt = 0; nt < 2; nt++) {
                const float* wr = sW + (warpN + nt * 8 + lr) * WROWF + s * 16 + lq * 2;
                float2 w0 = *(const float2*)wr;
                float2 w1 = *(const float2*)(wr + 8);
                __half2 h0 = __floats2half2_rn(w0.x, w0.y);
                __half2 h1 = __floats2half2_rn(w1.x, w1.y);
                uint32_t bh0 = *(uint32_t*)&h0, bh1 = *(uint32_t*)&h1;
#pragma unroll
                for (int mt = 0; mt < 4; mt++) mma16816(c[mt][nt], ahi[mt], bh0, bh1);
            }
        }
        if (++st == 3) st = 0;
    }

    // epilogue: add bias, store
#pragma unroll
    for (int nt = 0; nt < 2; nt++) {
        int col = v0 + warpN + nt * 8 + lq * 2;
        float b0 = 0.f, b1 = 0.f;
        if (col < VN) b0 = bias[col];
        if (col + 1 < VN) b1 = bias[col + 1];
#pragma unroll
        for (int mt = 0; mt < 4; mt++) {
            int row = warpM + mt * 16 + lr;
            if (col < VN) {
                out[(size_t)row * VN + col]       = c[mt][nt][0] + b0;
                out[(size_t)(row + 8) * VN + col] = c[mt][nt][2] + b0;
            }
            if (col + 1 < VN) {
                out[(size_t)row * VN + col + 1]       = c[mt][nt][1] + b1;
                out[(size_t)(row + 8) * VN + col + 1] = c[mt][nt][3] + b1;
            }
        }
    }
}

// ---------------- launch --------------------------------------------------------
extern "C" void kernel_launch(void* const* d_in, const int* in_sizes, int n_in,
                              void* d_out, int out_size) {
    const int*   x      = (const int*)d_in[0];
    const float* hidden = (const float*)d_in[1];
    const float* enc    = (const float*)d_in[2];
    const float* emb    = (const float*)d_in[3];
    const float* attn_w = (const float*)d_in[4];
    // d_in[5] = attn_b (softmax-invariant, unused)
    const float* v      = (const float*)d_in[6];
    const float* w_ih   = (const float*)d_in[7];
    const float* w_hh   = (const float*)d_in[8];
    const float* b_ih   = (const float*)d_in[9];
    const float* b_hh   = (const float*)d_in[10];
    const float* out_w  = (const float*)d_in[11];
    const float* out_b  = (const float*)d_in[12];
    float* out = (float*)d_out;

    cudaFuncSetAttribute(k_attn, cudaFuncAttributeMaxDynamicSharedMemorySize, ATTN_SMEM);
    cudaFuncSetAttribute(k_ggemm, cudaFuncAttributeMaxDynamicSharedMemorySize, GG_SMEM);
    cudaFuncSetAttribute(k_logits, cudaFuncAttributeMaxDynamicSharedMemorySize, LOG_SMEM);

    k_u2p<<<32, 256>>>(attn_w, v);
    k_attn<<<BN, 512, ATTN_SMEM>>>(enc, x, emb, hidden);
    k_ggemm<<<256, 256, GG_SMEM>>>(w_ih, w_hh);
    k_epiconv<<<BN, 512>>>(hidden, b_ih, b_hh, out + (size_t)BN * VN);
    k_logits<<<(VN + 63) / 64, 256, LOG_SMEM>>>(out_w, out_b, out);
}

// round 17
// speedup vs baseline: 1.0484x; 1.0101x over previous
#include <cuda_runtime.h>
#include <cuda_fp16.h>
#include <cstdint>

#define BN 128
#define HN 512
#define EN 256
#define VN 50000
#define SN 200
#define KT 1792     // 3H + E  (== GRU combined K)
#define GIN 1280    // 2H + E

// ---------------- device scratch (allocation-free rule: __device__ globals) ----
__device__ float g_u2p[32 * 1024];
__device__ float g_gp[4][BN * 2048];          // GRU gate partials (K-split 4)
__device__ int   g_ctr;                        // ggemm grid barrier counter
__device__ __align__(16) __half g_ah[BN * KT];    // to_out fp16 (logits A)
__device__ __align__(16) __half g_xh[BN * KT];    // GRU input X fp16

#define SWZ128(o) ((o) ^ (((o) >> 3) & 0x70))

__device__ __forceinline__ uint32_t smem_cast(const void* p) {
    return (uint32_t)__cvta_generic_to_shared(p);
}

#define CP_ASYNC16(s, g) asm volatile("cp.async.cg.shared.global [%0], [%1], 16;" :: "r"(s), "l"(g))
#define CP_COMMIT()      asm volatile("cp.async.commit_group;" ::: "memory")
#define CP_WAIT2()       asm volatile("cp.async.wait_group 2;" ::: "memory")
#define CP_WAIT1()       asm volatile("cp.async.wait_group 1;" ::: "memory")
#define CP_WAIT0()       asm volatile("cp.async.wait_group 0;" ::: "memory")

// ---------------- kernel 0: u2 partials; also resets ggemm barrier ctr ---------
__global__ void k_u2p(const float* __restrict__ aw, const float* __restrict__ v) {
    if (blockIdx.x == 0 && threadIdx.x == 0) g_ctr = 0;
    int g = blockIdx.x;
    for (int jj = 0; jj < 4; jj++) {
        int j = threadIdx.x + jj * 256;
        float acc = 0.f;
#pragma unroll
        for (int h = 0; h < 16; h++) {
            int hh = g * 16 + h;
            acc += v[hh] * aw[(size_t)hh * 1536 + 512 + j];
        }
        g_u2p[g * 1024 + j] = acc;
    }
}

// ---------------- kernel 1: attention (512 thr, 3-deep pipe) + A/X build -------
#define ATTN_SMEM ((3 * 16 * 1024 + 1024) * 4)

__global__ __launch_bounds__(512) void k_attn(const float* __restrict__ enc,
                                              const int* __restrict__ x,
                                              const float* __restrict__ emb,
                                              const float* __restrict__ hid) {
    extern __shared__ float sm[];
    float* s_enc = sm;                    // [3][16*1024]
    float* s_u2 = sm + 3 * 16 * 1024;     // [1024]
    __shared__ float s_sc[16];
    int tid = threadIdx.x, wid = tid >> 5, lid = tid & 31;
    int b = blockIdx.x;
    const float* base = enc + (size_t)b * SN * 1024;
    const int NT = 13;  // 12 x 16 + 8

#pragma unroll
    for (int t0 = 0; t0 < 2; t0++) {
        uint32_t sa = smem_cast(s_enc + t0 * 16 * 1024);
        const char* g = (const char*)(base + (size_t)t0 * 16 * 1024);
        for (int u = tid; u < 16 * 256; u += 512)
            CP_ASYNC16(sa + u * 16, g + (size_t)u * 16);
        CP_COMMIT();
    }

    for (int i = tid; i < 1024; i += 512) {
        float s = 0.f;
#pragma unroll
        for (int g = 0; g < 32; g++) s += g_u2p[g * 1024 + i];
        s_u2[i] = s;
    }

    float m = -1e30f, sum = 0.f;
    float c0 = 0.f, c1 = 0.f;
    int slot = 0;   // t % 3
    for (int t = 0; t < NT; t++) {
        float* buf = s_enc + slot * 16 * 1024;
        if (t + 2 < NT) {
            int nr2 = (t + 2 == NT - 1) ? (SN - 16 * (NT - 1)) : 16;
            int s2 = slot + 2; if (s2 >= 3) s2 -= 3;
            uint32_t sa = smem_cast(s_enc + s2 * 16 * 1024);
            const char* g = (const char*)(base + (size_t)(t + 2) * 16 * 1024);
            for (int u = tid; u < nr2 * 256; u += 512)
                CP_ASYNC16(sa + u * 16, g + (size_t)u * 16);
            CP_COMMIT();
            CP_WAIT2();
        } else if (t + 1 < NT) {
            CP_WAIT1();
        } else {
            CP_WAIT0();
        }
        __syncthreads();

        int nr = (t == NT - 1) ? (SN - 16 * (NT - 1)) : 16;
        const float4* u24 = (const float4*)s_u2;
        if (wid < nr) {
            const float4* row = (const float4*)(buf + wid * 1024);
            float acc = 0.f;
#pragma unroll
            for (int q = lid; q < 256; q += 32) {
                float4 e = row[q], u = u24[q];
                acc += e.x * u.x + e.y * u.y + e.z * u.z + e.w * u.w;
            }
#pragma unroll
            for (int o = 16; o; o >>= 1) acc += __shfl_xor_sync(0xffffffffu, acc, o);
            if (lid == 0) s_sc[wid] = acc;
        }
        __syncthreads();

        float nm = m;
        for (int j = 0; j < nr; j++) nm = fmaxf(nm, s_sc[j]);
        float scl = expf(m - nm);
        c0 *= scl; c1 *= scl; sum *= scl;
        for (int j = 0; j < nr; j++) {
            float p = expf(s_sc[j] - nm);
            sum += p;
            const float* r = buf + j * 1024;
            c0 += p * r[tid];
            c1 += p * r[tid + 512];
        }
        m = nm;
        __syncthreads();
        if (++slot == 3) slot = 0;
    }

    float inv = 1.0f / sum;
    c0 *= inv; c1 *= inv;

    int xb = b * KT;
    g_ah[xb + 512 + tid]  = __float2half_rn(c0);
    g_ah[xb + 1024 + tid] = __float2half_rn(c1);
    g_xh[xb + 256 + tid] = __float2half_rn(fmaxf(c0, 0.f));
    g_xh[xb + 768 + tid] = __float2half_rn(fmaxf(c1, 0.f));

    if (tid < 256) {
        float e = emb[(size_t)x[b] * EN + tid];
        g_ah[xb + 1536 + tid] = __float2half_rn(e);
        g_xh[xb + tid] = __float2half_rn(fmaxf(e, 0.f));
    }
    float h0 = hid[b * HN + tid];
    g_xh[xb + 1280 + tid] = __float2half_rn(h0);
}

// ---------------- shared GEMM constants ----------------------------------------
#define ABYTES 16384
#define WROWF  68                      // 64 + 4 pad floats per row
#define NCHUNK 28

__device__ __forceinline__ void mma16816(float* c, const uint32_t* a, uint32_t b0, uint32_t b1) {
    asm volatile(
        "mma.sync.aligned.m16n8k16.row.col.f32.f16.f16.f32 "
        "{%0,%1,%2,%3}, {%4,%5,%6,%7}, {%8,%9}, {%0,%1,%2,%3};"
        : "+f"(c[0]), "+f"(c[1]), "+f"(c[2]), "+f"(c[3])
        : "r"(a[0]), "r"(a[1]), "r"(a[2]), "r"(a[3]), "r"(b0), "r"(b1));
}

__device__ __forceinline__ void stage_a256(int ch, uint32_t sbase, int tid, const char* ah) {
#pragma unroll
    for (int i = 0; i < 4; i++) {
        int q = tid + i * 256;
        int row = q >> 3, seg = q & 7;
        uint32_t sw = SWZ128((uint32_t)(row * 128 + seg * 16));
        CP_ASYNC16(sbase + sw, ah + (size_t)ch * 128 + (size_t)row * (KT * 2) + seg * 16);
    }
}

// ---------------- kernel 2: GRU gate GEMM + fused epilogue (grid barrier) ------
// grid = 256 CTAs, all co-resident (2/SM guaranteed by launch_bounds + smem).
// After partial stores: threadfence -> atomic arrive -> spin -> distributed
// epilogue: 256 CTAs x 256 thr = 65536 threads = one (b,k) each.
#define GG_WBYTES (32 * WROWF * 4)       // 8704
#define GG_SSTG   (ABYTES + GG_WBYTES)   // 25088
#define GG_SMEM   (2 * GG_SSTG)          // 50176

__global__ __launch_bounds__(256, 2) void k_ggemm(const float* __restrict__ wih,
                                                  const float* __restrict__ whh,
                                                  const float* __restrict__ hid,
                                                  const float* __restrict__ bih,
                                                  const float* __restrict__ bhh,
                                                  float* __restrict__ outh) {
    extern __shared__ char smem[];
    int tid = threadIdx.x, wid = tid >> 5, lid = tid & 31;
    int t = blockIdx.x >> 2;            // n-tile 0..63 (32 cols each)
    int ks = blockIdx.x & 3;            // k-slice 0..3
    int j0 = t * 32;
    int ch0 = (t >= 48) ? 20 : 0;
    int ch1 = (t >= 32 && t < 48) ? 20 : NCHUNK;
    int cl0 = max(ch0, ks * 7), cl1 = min(ch1, ks * 7 + 7);

    float* gp = g_gp[ks];

    if (cl0 >= cl1) {                   // empty slice: zero the partial
        for (int i = tid; i < 128 * 32; i += 256) {
            int row = i >> 5, col = i & 31;
            gp[row * 2048 + j0 + col] = 0.f;
        }
    } else {
        int warpM = (wid & 3) * 32;
        int warpN = (wid >> 2) * 16;
        int lr = lid >> 2, lq = lid & 3;
        int lrow = lid & 15;
        int lcolh = (lid >> 4) * 16;

        uint32_t sb = smem_cast(smem);
        const char* ah = (const char*)g_xh;

        float c[2][2][4];
#pragma unroll
        for (int mt = 0; mt < 2; mt++)
#pragma unroll
            for (int nt = 0; nt < 2; nt++)
#pragma unroll
                for (int j = 0; j < 4; j++) c[mt][nt][j] = 0.f;

        auto stage_w = [&](int ch, uint32_t sbase) {
            uint32_t sa_w = sbase + ABYTES;
#pragma unroll
            for (int i = 0; i < 2; i++) {
                int u = tid + i * 256;
                int row = u >> 4, seg = u & 15;
                int j = j0 + row;
                const char* src;
                if (ch < 20) {
                    src = (const char*)(wih + (size_t)j * GIN + ch * 64);
                } else {
                    int wr = (j < 1024) ? j : j - 512;
                    src = (const char*)(whh + (size_t)wr * HN + (ch - 20) * 64);
                }
                CP_ASYNC16(sa_w + row * (WROWF * 4) + seg * 16, src + seg * 16);
            }
        };

        stage_a256(cl0, sb, tid, ah);
        stage_w(cl0, sb);
        CP_COMMIT();
        if (cl0 + 1 < cl1) {
            stage_a256(cl0 + 1, sb + GG_SSTG, tid, ah);
            stage_w(cl0 + 1, sb + GG_SSTG);
            CP_COMMIT();
        }

        for (int ch = cl0; ch < cl1; ch++) {
            if (ch == cl1 - 1) { CP_WAIT0(); } else { CP_WAIT1(); }
            __syncthreads();

            int st = (ch - cl0) & 1;
            uint32_t sa_hi = sb + (uint32_t)st * GG_SSTG;
            const float* sW = (const float*)(smem + st * GG_SSTG + ABYTES);

#pragma unroll
            for (int s = 0; s < 4; s++) {
                uint32_t ahi[2][4];
#pragma unroll
                for (int mt = 0; mt < 2; mt++) {
                    int row = warpM + mt * 16 + lrow;
                    uint32_t off = SWZ128((uint32_t)(row * 128 + s * 32 + lcolh));
                    asm volatile("ldmatrix.sync.aligned.m8n8.x4.shared.b16 {%0,%1,%2,%3}, [%4];"
                                 : "=r"(ahi[mt][0]), "=r"(ahi[mt][1]), "=r"(ahi[mt][2]), "=r"(ahi[mt][3])
                                 : "r"(sa_hi + off));
                }
#pragma unroll
                for (int nt = 0; nt < 2; nt++) {
                    const float* wr = sW + (warpN + nt * 8 + lr) * WROWF + s * 16 + lq * 2;
                    float2 w0 = *(const float2*)wr;
                    float2 w1 = *(const float2*)(wr + 8);
                    __half2 h0 = __floats2half2_rn(w0.x, w0.y);
                    __half2 h1 = __floats2half2_rn(w1.x, w1.y);
                    uint32_t bh0 = *(uint32_t*)&h0, bh1 = *(uint32_t*)&h1;
#pragma unroll
                    for (int mt = 0; mt < 2; mt++) mma16816(c[mt][nt], ahi[mt], bh0, bh1);
                }
            }
            __syncthreads();
            if (ch + 2 < cl1) {
                uint32_t sbuf2 = sb + (uint32_t)((ch - cl0) & 1) * GG_SSTG;
                stage_a256(ch + 2, sbuf2, tid, ah);
                stage_w(ch + 2, sbuf2);
                CP_COMMIT();
            }
        }

#pragma unroll
        for (int nt = 0; nt < 2; nt++) {
            int col = j0 + warpN + nt * 8 + lq * 2;
#pragma unroll
            for (int mt = 0; mt < 2; mt++) {
                int row = warpM + mt * 16 + lr;
                gp[row * 2048 + col]           = c[mt][nt][0];
                gp[row * 2048 + col + 1]       = c[mt][nt][1];
                gp[(row + 8) * 2048 + col]     = c[mt][nt][2];
                gp[(row + 8) * 2048 + col + 1] = c[mt][nt][3];
            }
        }
    }

    // ---- grid-wide barrier (all 256 CTAs co-resident: see launch_bounds) ----
    __syncthreads();
    if (tid == 0) {
        __threadfence();
        atomicAdd(&g_ctr, 1);
        while (atomicAdd(&g_ctr, 0) < 256) {}
    }
    __syncthreads();
    __threadfence();

    // ---- distributed GRU epilogue: one (b, k) per thread ----
    {
        int gt = blockIdx.x * 256 + tid;      // 0..65535
        int b = gt >> 9;                      // 0..127
        int k = gt & 511;                     // 0..511
        int gb = b * 2048;
        float gr = g_gp[0][gb + k] + g_gp[1][gb + k] + g_gp[2][gb + k] + g_gp[3][gb + k];
        float gz = g_gp[0][gb + 512 + k] + g_gp[1][gb + 512 + k] + g_gp[2][gb + 512 + k] + g_gp[3][gb + 512 + k];
        float gi = g_gp[0][gb + 1024 + k] + g_gp[1][gb + 1024 + k] + g_gp[2][gb + 1024 + k] + g_gp[3][gb + 1024 + k];
        float gh = g_gp[0][gb + 1536 + k] + g_gp[1][gb + 1536 + k] + g_gp[2][gb + 1536 + k] + g_gp[3][gb + 1536 + k];
        float h0 = hid[b * HN + k];
        float r = 1.f / (1.f + expf(-(gr + bih[k] + bhh[k])));
        float z = 1.f / (1.f + expf(-(gz + bih[512 + k] + bhh[512 + k])));
        float n = tanhf(gi + bih[1024 + k] + r * (gh + bhh[1024 + k]));
        float h = (1.f - z) * n + z * h0;
        outh[b * HN + k] = h;
        g_ah[b * KT + k] = __float2half_rn(h);
    }
}

// ---------------- kernel 3: logits — R13 config (per-tile, 3-stage, 1 barrier) -
#define LG_WBYTES (64 * WROWF * 4)       // 17408
#define LG_SSTG   (ABYTES + LG_WBYTES)   // 33792
#define LOG_SMEM  (3 * LG_SSTG)          // 101376

__device__ __forceinline__ void stage_chunk_l(int ch, uint32_t sbase, int tid,
                                              const char* ah, const float* W, int v0) {
    stage_a256(ch, sbase, tid, ah);
    uint32_t sa_w = sbase + ABYTES;
#pragma unroll
    for (int i = 0; i < 4; i++) {
        int u = tid + i * 256;
        int row = u >> 4, seg = u & 15;
        int vr = v0 + row;
        if (vr >= VN) vr = VN - 1;
        CP_ASYNC16(sa_w + row * (WROWF * 4) + seg * 16,
                   (const char*)(W + (size_t)vr * KT + ch * 64) + seg * 16);
    }
    CP_COMMIT();
}

__global__ __launch_bounds__(256, 2) void k_logits(const float* __restrict__ W,
                                                   const float* __restrict__ bias,
                                                   float* __restrict__ out) {
    extern __shared__ char smem[];
    int tid = threadIdx.x, wid = tid >> 5, lid = tid & 31;
    int v0 = blockIdx.x * 64;
    int warpM = (wid & 1) * 64;
    int warpN = (wid >> 1) * 16;
    int lr = lid >> 2, lq = lid & 3;
    int lrow = lid & 15;
    int lcolh = (lid >> 4) * 16;

    uint32_t sb = smem_cast(smem);
    const char* ah = (const char*)g_ah;

    float c[4][2][4];
#pragma unroll
    for (int mt = 0; mt < 4; mt++)
#pragma unroll
        for (int nt = 0; nt < 2; nt++)
#pragma unroll
            for (int j = 0; j < 4; j++) c[mt][nt][j] = 0.f;

    stage_chunk_l(0, sb, tid, ah, W, v0);
    stage_chunk_l(1, sb + LG_SSTG, tid, ah, W, v0);

    int st = 0;                          // st = ch % 3
    for (int ch = 0; ch < NCHUNK; ch++) {
        if (ch == NCHUNK - 1) { CP_WAIT0(); } else { CP_WAIT1(); }
        __syncthreads();                 // single barrier per chunk

        if (ch + 2 < NCHUNK) {
            int st2 = st + 2; if (st2 >= 3) st2 -= 3;
            stage_chunk_l(ch + 2, sb + (uint32_t)st2 * LG_SSTG, tid, ah, W, v0);
        }

        uint32_t sa_hi = sb + (uint32_t)st * LG_SSTG;
        const float* sW = (const float*)(smem + st * LG_SSTG + ABYTES);

#pragma unroll
        for (int s = 0; s < 4; s++) {
            uint32_t ahi[4][4];
#pragma unroll
            for (int mt = 0; mt < 4; mt++) {
                int row = warpM + mt * 16 + lrow;
                uint32_t off = SWZ128((uint32_t)(row * 128 + s * 32 + lcolh));
                asm volatile("ldmatrix.sync.aligned.m8n8.x4.shared.b16 {%0,%1,%2,%3}, [%4];"
                             : "=r"(ahi[mt][0]), "=r"(ahi[mt][1]), "=r"(ahi[mt][2]), "=r"(ahi[mt][3])
                             : "r"(sa_hi + off));
            }
#pragma unroll
            for (int nt = 0; nt < 2; nt++) {
                const float* wr = sW + (warpN + nt * 8 + lr) * WROWF + s * 16 + lq * 2;
                float2 w0 = *(const float2*)wr;
                float2 w1 = *(const float2*)(wr + 8);
                __half2 h0 = __floats2half2_rn(w0.x, w0.y);
                __half2 h1 = __floats2half2_rn(w1.x, w1.y);
                uint32_t bh0 = *(uint32_t*)&h0, bh1 = *(uint32_t*)&h1;
#pragma unroll
                for (int mt = 0; mt < 4; mt++) mma16816(c[mt][nt], ahi[mt], bh0, bh1);
            }
        }
        if (++st == 3) st = 0;
    }

    // epilogue: add bias, store
#pragma unroll
    for (int nt = 0; nt < 2; nt++) {
        int col = v0 + warpN + nt * 8 + lq * 2;
        float b0 = 0.f, b1 = 0.f;
        if (col < VN) b0 = bias[col];
        if (col + 1 < VN) b1 = bias[col + 1];
#pragma unroll
        for (int mt = 0; mt < 4; mt++) {
            int row = warpM + mt * 16 + lr;
            if (col < VN) {
                out[(size_t)row * VN + col]       = c[mt][nt][0] + b0;
                out[(size_t)(row + 8) * VN + col] = c[mt][nt][2] + b0;
            }
            if (col + 1 < VN) {
                out[(size_t)row * VN + col + 1]       = c[mt][nt][1] + b1;
                out[(size_t)(row + 8) * VN + col + 1] = c[mt][nt][3] + b1;
            }
        }
    }
}

// ---------------- launch --------------------------------------------------------
extern "C" void kernel_launch(void* const* d_in, const int* in_sizes, int n_in,
                              void* d_out, int out_size) {
    const int*   x      = (const int*)d_in[0];
    const float* hidden = (const float*)d_in[1];
    const float* enc    = (const float*)d_in[2];
    const float* emb    = (const float*)d_in[3];
    const float* attn_w = (const float*)d_in[4];
    // d_in[5] = attn_b (softmax-invariant, unused)
    const float* v      = (const float*)d_in[6];
    const float* w_ih   = (const float*)d_in[7];
    const float* w_hh   = (const float*)d_in[8];
    const float* b_ih   = (const float*)d_in[9];
    const float* b_hh   = (const float*)d_in[10];
    const float* out_w  = (const float*)d_in[11];
    const float* out_b  = (const float*)d_in[12];
    float* out = (float*)d_out;

    cudaFuncSetAttribute(k_attn, cudaFuncAttributeMaxDynamicSharedMemorySize, ATTN_SMEM);
    cudaFuncSetAttribute(k_ggemm, cudaFuncAttributeMaxDynamicSharedMemorySize, GG_SMEM);
    cudaFuncSetAttribute(k_logits, cudaFuncAttributeMaxDynamicSharedMemorySize, LOG_SMEM);

    k_u2p<<<32, 256>>>(attn_w, v);
    k_attn<<<BN, 512, ATTN_SMEM>>>(enc, x, emb, hidden);
    k_ggemm<<<256, 256, GG_SMEM>>>(w_ih, w_hh, hidden, b_ih, b_hh,
                                   out + (size_t)BN * VN);
    k_logits<<<(VN + 63) / 64, 256, LOG_SMEM>>>(out_w, out_b, out);
}